// round 1
// baseline (speedup 1.0000x reference)
#include <cuda_runtime.h>
#include <math.h>

// ---------------------------------------------------------------------------
// AlphaRotatedIoULoss: per-pair rotated-box IoU -> loss = 1 - iou^3, mean.
// Faithful re-implementation of the JAX reference, including its
// "missing wrap term" shoelace semantics (masked slots contribute zeros).
// ---------------------------------------------------------------------------

#define ALPHA_EPS 1e-6f

__device__ double g_loss_acc;

__global__ void zero_acc_kernel() { g_loss_acc = 0.0; }

__global__ void finalize_kernel(float* out, float inv_n) {
    out[0] = (float)(g_loss_acc * (double)inv_n);
}

__device__ __forceinline__ float cross2(float ax, float ay, float bx, float by) {
    return ax * by - ay * bx;
}

__global__ __launch_bounds__(256)
void rotated_iou_loss_kernel(const float* __restrict__ pred,
                             const float* __restrict__ target,
                             const float* __restrict__ weight,
                             int n)
{
    int i = blockIdx.x * blockDim.x + threadIdx.x;
    float loss = 0.0f;

    if (i < n) {
        // --- load boxes ---
        float p_x = pred[i * 5 + 0];
        float p_y = pred[i * 5 + 1];
        float p_w = pred[i * 5 + 2];
        float p_h = pred[i * 5 + 3];
        float p_a = pred[i * 5 + 4];

        float t_x = target[i * 5 + 0];
        float t_y = target[i * 5 + 1];
        float t_w = target[i * 5 + 2];
        float t_h = target[i * 5 + 3];
        float t_a = target[i * 5 + 4];

        // --- corners (same dx/dy order as reference) ---
        const float dxs[4] = { 0.5f, -0.5f, -0.5f,  0.5f };
        const float dys[4] = { 0.5f,  0.5f, -0.5f, -0.5f };

        float pc, ps, tc, ts;
        sincosf(p_a, &ps, &pc);
        sincosf(t_a, &ts, &tc);

        float c1x[4], c1y[4], c2x[4], c2y[4];
        #pragma unroll
        for (int j = 0; j < 4; j++) {
            float lx = p_w * dxs[j];
            float ly = p_h * dys[j];
            c1x[j] = p_x + lx * pc - ly * ps;
            c1y[j] = p_y + lx * ps + ly * pc;
            float lx2 = t_w * dxs[j];
            float ly2 = t_h * dys[j];
            c2x[j] = t_x + lx2 * tc - ly2 * ts;
            c2y[j] = t_y + lx2 * ts + ly2 * tc;
        }

        // --- candidate points: 16 edge intersections, then c1, then c2 ---
        float X[24], Y[24];
        int m = 0;
        float sx = 0.0f, sy = 0.0f;

        #pragma unroll
        for (int j = 0; j < 4; j++) {
            float p1x = c1x[j], p1y = c1y[j];
            float d1x = c1x[(j + 1) & 3] - p1x;
            float d1y = c1y[(j + 1) & 3] - p1y;
            #pragma unroll
            for (int k = 0; k < 4; k++) {
                float p2x = c2x[k], p2y = c2y[k];
                float d2x = c2x[(k + 1) & 3] - p2x;
                float d2y = c2y[(k + 1) & 3] - p2y;
                float den = cross2(d1x, d1y, d2x, d2y);
                if (fabsf(den) > 1e-8f) {
                    float rpx = p2x - p1x;
                    float rpy = p2y - p1y;
                    float tpar = cross2(rpx, rpy, d2x, d2y) / den;
                    float upar = cross2(rpx, rpy, d1x, d1y) / den;
                    if (tpar >= 0.0f && tpar <= 1.0f && upar >= 0.0f && upar <= 1.0f) {
                        float ix = p1x + tpar * d1x;
                        float iy = p1y + tpar * d1y;
                        X[m] = ix; Y[m] = iy;
                        sx += ix; sy += iy;
                        m++;
                    }
                }
            }
        }

        // pred corners inside target box
        const float tol = 1e-6f;
        {
            float hw = t_w * 0.5f + tol;
            float hh = t_h * 0.5f + tol;
            #pragma unroll
            for (int j = 0; j < 4; j++) {
                float dx = c1x[j] - t_x;
                float dy = c1y[j] - t_y;
                float u =  dx * tc + dy * ts;
                float v = -dx * ts + dy * tc;
                if (fabsf(u) <= hw && fabsf(v) <= hh) {
                    X[m] = c1x[j]; Y[m] = c1y[j];
                    sx += c1x[j]; sy += c1y[j];
                    m++;
                }
            }
        }
        // target corners inside pred box
        {
            float hw = p_w * 0.5f + tol;
            float hh = p_h * 0.5f + tol;
            #pragma unroll
            for (int j = 0; j < 4; j++) {
                float dx = c2x[j] - p_x;
                float dy = c2y[j] - p_y;
                float u =  dx * pc + dy * ps;
                float v = -dx * ps + dy * pc;
                if (fabsf(u) <= hw && fabsf(v) <= hh) {
                    X[m] = c2x[j]; Y[m] = c2y[j];
                    sx += c2x[j]; sy += c2y[j];
                    m++;
                }
            }
        }

        // --- centroid (cnt clamped to >=1 as in reference) ---
        float cnt = fmaxf((float)m, 1.0f);
        float mx = sx / cnt;
        float my = sy / cnt;

        // --- relative coords + angle, stable insertion sort by angle ---
        float ang[24];
        for (int t = 0; t < m; t++) {
            X[t] -= mx;
            Y[t] -= my;
            ang[t] = atan2f(Y[t], X[t]);
        }
        for (int a = 1; a < m; a++) {
            float ka = ang[a], kx = X[a], ky = Y[a];
            int b = a - 1;
            while (b >= 0 && ang[b] > ka) {
                ang[b + 1] = ang[b];
                X[b + 1] = X[b];
                Y[b + 1] = Y[b];
                b--;
            }
            ang[b + 1] = ka;
            X[b + 1] = kx;
            Y[b + 1] = ky;
        }

        // --- shoelace, reproducing reference's zero-padded roll semantics:
        //     the wrap term cross(v_{m-1}, v_0) is INCLUDED only if m == 24.
        float s = 0.0f;
        for (int t = 0; t + 1 < m; t++) {
            s += X[t] * Y[t + 1] - Y[t] * X[t + 1];
        }
        if (m == 24) {
            s += X[23] * Y[0] - Y[23] * X[0];
        }
        float inter = 0.5f * fabsf(s);

        float uni = p_w * p_h + t_w * t_h - inter;
        float iou = inter / fmaxf(uni, ALPHA_EPS);
        iou = fmaxf(iou, ALPHA_EPS);
        loss = (1.0f - iou * iou * iou) * weight[i];
    }

    // --- block reduction -> one double atomicAdd per block ---
    #pragma unroll
    for (int o = 16; o > 0; o >>= 1)
        loss += __shfl_down_sync(0xFFFFFFFFu, loss, o);

    __shared__ float warp_sums[8];
    int lane = threadIdx.x & 31;
    int wid  = threadIdx.x >> 5;
    if (lane == 0) warp_sums[wid] = loss;
    __syncthreads();

    if (wid == 0) {
        float v = (lane < 8) ? warp_sums[lane] : 0.0f;
        #pragma unroll
        for (int o = 4; o > 0; o >>= 1)
            v += __shfl_down_sync(0xFFFFFFFFu, v, o);
        if (lane == 0)
            atomicAdd(&g_loss_acc, (double)v);
    }
}

extern "C" void kernel_launch(void* const* d_in, const int* in_sizes, int n_in,
                              void* d_out, int out_size) {
    const float* pred   = (const float*)d_in[0];
    const float* target = (const float*)d_in[1];
    const float* wgt    = (const float*)d_in[2];
    float* out = (float*)d_out;

    int n = in_sizes[2];            // weight has n elements; pred/target have 5n
    if (n * 5 != in_sizes[0]) n = in_sizes[0] / 5;  // defensive

    zero_acc_kernel<<<1, 1>>>();
    int threads = 256;
    int blocks = (n + threads - 1) / threads;
    rotated_iou_loss_kernel<<<blocks, threads>>>(pred, target, wgt, n);
    finalize_kernel<<<1, 1>>>(out, 1.0f / (float)n);
}